// round 1
// baseline (speedup 1.0000x reference)
#include <cuda_runtime.h>

#define DDIM 128
#define MAXN 50048

// Scratch (allocation-free: __device__ globals)
__device__ float g_agg[(size_t)MAXN * DDIM];
__device__ float g_h  [(size_t)MAXN * DDIM];
__device__ float g_x  [(size_t)MAXN * DDIM];

// ---------------------------------------------------------------------------
// agg = x  (vectorized copy)
// ---------------------------------------------------------------------------
__global__ void copy_kernel(float* __restrict__ dst, const float* __restrict__ src, int n4) {
    int i = blockIdx.x * blockDim.x + threadIdx.x;
    if (i < n4) ((float4*)dst)[i] = ((const float4*)src)[i];
}

// ---------------------------------------------------------------------------
// agg[dst] += x[src] for every edge.  One warp per edge, lane handles 4 cols.
// Edge dtype (int64 vs int32) self-detected from data.
// ---------------------------------------------------------------------------
__global__ void scatter_kernel(float* __restrict__ agg, const float* __restrict__ x,
                               const void* __restrict__ ei, int E, int N) {
    long long gw = (long long)blockIdx.x * (blockDim.x >> 5) + (threadIdx.x >> 5);
    if (gw >= E) return;
    int lane = threadIdx.x & 31;

    const long long* e64 = (const long long*)ei;
    const int*       e32 = (const int*)ei;

    bool is64 = true;
#pragma unroll
    for (int i = 0; i < 4; i++) {
        long long v = e64[i];
        if (v < 0 || v >= (long long)N) is64 = false;
    }

    long long s, d;
    if (is64) { s = e64[gw]; d = e64[E + gw]; }
    else      { s = (long long)e32[gw]; d = (long long)e32[E + gw]; }

    float4 v = ((const float4*)(x + s * DDIM))[lane];
    float* o = agg + d * DDIM + (lane << 2);
    atomicAdd(o + 0, v.x);
    atomicAdd(o + 1, v.y);
    atomicAdd(o + 2, v.z);
    atomicAdd(o + 3, v.w);
}

// ---------------------------------------------------------------------------
// C[M,128] = relu(A[M,128] @ W[128,128] + bias)
// 128x128 block tile, BK=32, 256 threads, 8x8 microtile per thread.
// ---------------------------------------------------------------------------
__global__ void __launch_bounds__(256, 2)
gemm_bias_relu(const float* __restrict__ A, const float* __restrict__ W,
               const float* __restrict__ bias, float* __restrict__ C, int M) {
    __shared__ float As[32][128];   // [k][row]   (transposed A tile)
    __shared__ float Bs[32][128];   // [k][col]

    int tid = threadIdx.x;
    int tx = tid & 15;          // 0..15  -> 8 output cols each
    int ty = tid >> 4;          // 0..15  -> 8 output rows each
    int row0 = blockIdx.x * 128;

    float acc[8][8];
#pragma unroll
    for (int i = 0; i < 8; i++)
#pragma unroll
        for (int j = 0; j < 8; j++) acc[i][j] = 0.f;

    for (int kt = 0; kt < 128; kt += 32) {
        // Load A tile (128 rows x 32 k), store transposed
#pragma unroll
        for (int i = 0; i < 4; i++) {
            int idx = (tid + i * 256) * 4;       // 0..4095
            int r = idx >> 5;                    // row in tile
            int c = idx & 31;                    // k within tile (mult of 4)
            float4 v = make_float4(0.f, 0.f, 0.f, 0.f);
            int gr = row0 + r;
            if (gr < M) v = *(const float4*)(A + (size_t)gr * 128 + kt + c);
            As[c + 0][r] = v.x;
            As[c + 1][r] = v.y;
            As[c + 2][r] = v.z;
            As[c + 3][r] = v.w;
        }
        // Load B tile (32 k x 128 cols)
#pragma unroll
        for (int i = 0; i < 4; i++) {
            int idx = (tid + i * 256) * 4;
            int r = idx >> 7;
            int c = idx & 127;
            *(float4*)&Bs[r][c] = *(const float4*)(W + (size_t)(kt + r) * 128 + c);
        }
        __syncthreads();

#pragma unroll
        for (int k = 0; k < 32; k++) {
            float4 a0 = *(float4*)&As[k][ty * 8];
            float4 a1 = *(float4*)&As[k][ty * 8 + 4];
            float4 b0 = *(float4*)&Bs[k][tx * 8];
            float4 b1 = *(float4*)&Bs[k][tx * 8 + 4];
            float a[8] = {a0.x, a0.y, a0.z, a0.w, a1.x, a1.y, a1.z, a1.w};
            float b[8] = {b0.x, b0.y, b0.z, b0.w, b1.x, b1.y, b1.z, b1.w};
#pragma unroll
            for (int i = 0; i < 8; i++)
#pragma unroll
                for (int j = 0; j < 8; j++)
                    acc[i][j] += a[i] * b[j];
        }
        __syncthreads();
    }

    // Epilogue: bias + relu, vectorized store
#pragma unroll
    for (int i = 0; i < 8; i++) {
        int gr = row0 + ty * 8 + i;
        if (gr >= M) continue;
#pragma unroll
        for (int jj = 0; jj < 2; jj++) {
            int c = tx * 8 + jj * 4;
            float4 o;
            o.x = fmaxf(acc[i][jj * 4 + 0] + bias[c + 0], 0.f);
            o.y = fmaxf(acc[i][jj * 4 + 1] + bias[c + 1], 0.f);
            o.z = fmaxf(acc[i][jj * 4 + 2] + bias[c + 2], 0.f);
            o.w = fmaxf(acc[i][jj * 4 + 3] + bias[c + 3], 0.f);
            *(float4*)(C + (size_t)gr * 128 + c) = o;
        }
    }
}

// ---------------------------------------------------------------------------
extern "C" void kernel_launch(void* const* d_in, const int* in_sizes, int n_in,
                              void* d_out, int out_size) {
    const float* x  = (const float*)d_in[0];
    const void*  ei = d_in[1];
    const float* W1 = (const float*)d_in[2];
    const float* b1 = (const float*)d_in[3];
    const float* W2 = (const float*)d_in[4];
    const float* b2 = (const float*)d_in[5];

    int N = in_sizes[0] / DDIM;
    int E = in_sizes[1] / 2;
    int L = in_sizes[3] / DDIM;   // b1 is [L, D]

    float* out = (float*)d_out;

    float *agg, *h, *xb;
    cudaGetSymbolAddress((void**)&agg, g_agg);
    cudaGetSymbolAddress((void**)&h,   g_h);
    cudaGetSymbolAddress((void**)&xb,  g_x);

    const float* cur = x;
    int n4 = N * (DDIM / 4);
    int copy_blocks = (n4 + 255) / 256;
    int scat_blocks = (E + 7) / 8;          // 8 warps / block
    int gemm_blocks = (N + 127) / 128;

    for (int l = 0; l < L; l++) {
        copy_kernel<<<copy_blocks, 256>>>(agg, cur, n4);
        scatter_kernel<<<scat_blocks, 256>>>(agg, cur, ei, E, N);
        gemm_bias_relu<<<gemm_blocks, 256>>>(agg, W1 + (size_t)l * DDIM * DDIM,
                                             b1 + (size_t)l * DDIM, h, N);
        float* dst = (l == L - 1) ? out : xb;
        gemm_bias_relu<<<gemm_blocks, 256>>>(h, W2 + (size_t)l * DDIM * DDIM,
                                             b2 + (size_t)l * DDIM, dst, N);
        cur = dst;
    }
}

// round 2
// speedup vs baseline: 2.0500x; 2.0500x over previous
#include <cuda_runtime.h>

#define DDIM 128
#define MAXN 50048
#define MAXE 2097152

// Scratch (allocation-free: __device__ globals)
__device__ float g_agg[(size_t)MAXN * DDIM];
__device__ float g_h  [(size_t)MAXN * DDIM];
__device__ float g_x  [(size_t)MAXN * DDIM];
__device__ int   g_cnt[MAXN];
__device__ int   g_rowptr[MAXN + 1];
__device__ int   g_cursor[MAXN];
__device__ int   g_esrc[MAXE];

// ---------------------------------------------------------------------------
// Edge dtype self-detection (int64 vs int32): check first 4 values as int64.
// ---------------------------------------------------------------------------
__device__ __forceinline__ bool edges_are_i64(const void* ei, int N) {
    const long long* e64 = (const long long*)ei;
#pragma unroll
    for (int i = 0; i < 4; i++) {
        long long v = e64[i];
        if (v < 0 || v >= (long long)N) return false;
    }
    return true;
}

__global__ void zero_cnt_kernel(int* cnt, int n) {
    int i = blockIdx.x * blockDim.x + threadIdx.x;
    if (i < n) cnt[i] = 0;
}

__global__ void hist_kernel(int* cnt, const void* ei, int E, int N) {
    int i = blockIdx.x * blockDim.x + threadIdx.x;
    if (i >= E) return;
    bool is64 = edges_are_i64(ei, N);
    int d;
    if (is64) d = (int)((const long long*)ei)[E + i];
    else      d = ((const int*)ei)[E + i];
    atomicAdd(&cnt[d], 1);
}

// One-block exclusive scan over N counts -> rowptr[0..N], cursor copy.
__global__ void scan_kernel(const int* __restrict__ cnt, int* __restrict__ rowptr,
                            int* __restrict__ cursor, int N) {
    __shared__ int part[1024];
    int tid = threadIdx.x;
    int chunk = (N + 1023) / 1024;
    int start = tid * chunk;
    int end = min(start + chunk, N);
    int s = 0;
    for (int i = start; i < end; i++) s += cnt[i];
    part[tid] = s;
    __syncthreads();
    for (int off = 1; off < 1024; off <<= 1) {
        int v = (tid >= off) ? part[tid - off] : 0;
        __syncthreads();
        part[tid] += v;
        __syncthreads();
    }
    int run = (tid == 0) ? 0 : part[tid - 1];
    for (int i = start; i < end; i++) {
        rowptr[i] = run;
        cursor[i] = run;
        run += cnt[i];
    }
    if (end == N) rowptr[N] = run;
}

__global__ void bucket_kernel(int* __restrict__ cursor, int* __restrict__ esrc,
                              const void* ei, int E, int N) {
    int i = blockIdx.x * blockDim.x + threadIdx.x;
    if (i >= E) return;
    bool is64 = edges_are_i64(ei, N);
    int s, d;
    if (is64) {
        s = (int)((const long long*)ei)[i];
        d = (int)((const long long*)ei)[E + i];
    } else {
        s = ((const int*)ei)[i];
        d = ((const int*)ei)[E + i];
    }
    int pos = atomicAdd(&cursor[d], 1);
    esrc[pos] = s;
}

// ---------------------------------------------------------------------------
// agg[i] = x[i] + sum_{s in in-neighbors(i)} x[s].  One warp per node.
// Edge src indices pre-loaded per 32-edge chunk (coalesced), broadcast via shfl.
// ---------------------------------------------------------------------------
__global__ void gather_agg_kernel(float* __restrict__ agg, const float* __restrict__ x,
                                  const int* __restrict__ rowptr,
                                  const int* __restrict__ esrc, int N) {
    int node = blockIdx.x * (blockDim.x >> 5) + (threadIdx.x >> 5);
    if (node >= N) return;
    int lane = threadIdx.x & 31;

    float4 acc = ((const float4*)(x + (size_t)node * DDIM))[lane];
    int b = rowptr[node];
    int e = rowptr[node + 1];

    for (int base = b; base < e; base += 32) {
        int m = min(32, e - base);
        int sv = (lane < m) ? esrc[base + lane] : 0;
#pragma unroll 4
        for (int j = 0; j < m; j++) {
            int s = __shfl_sync(0xffffffffu, sv, j);
            float4 v = ((const float4*)(x + (size_t)s * DDIM))[lane];
            acc.x += v.x; acc.y += v.y; acc.z += v.z; acc.w += v.w;
        }
    }
    ((float4*)(agg + (size_t)node * DDIM))[lane] = acc;
}

// ---------------------------------------------------------------------------
// C[M,128] = relu(A[M,128] @ W[128,128] + bias)
// 128x128 block tile, BK=32, 256 threads, 8x8 microtile per thread.
// ---------------------------------------------------------------------------
__global__ void __launch_bounds__(256, 2)
gemm_bias_relu(const float* __restrict__ A, const float* __restrict__ W,
               const float* __restrict__ bias, float* __restrict__ C, int M) {
    __shared__ float As[32][128];   // [k][row]   (transposed A tile)
    __shared__ float Bs[32][128];   // [k][col]

    int tid = threadIdx.x;
    int tx = tid & 15;
    int ty = tid >> 4;
    int row0 = blockIdx.x * 128;

    float acc[8][8];
#pragma unroll
    for (int i = 0; i < 8; i++)
#pragma unroll
        for (int j = 0; j < 8; j++) acc[i][j] = 0.f;

    for (int kt = 0; kt < 128; kt += 32) {
#pragma unroll
        for (int i = 0; i < 4; i++) {
            int idx = (tid + i * 256) * 4;
            int r = idx >> 5;
            int c = idx & 31;
            float4 v = make_float4(0.f, 0.f, 0.f, 0.f);
            int gr = row0 + r;
            if (gr < M) v = *(const float4*)(A + (size_t)gr * 128 + kt + c);
            As[c + 0][r] = v.x;
            As[c + 1][r] = v.y;
            As[c + 2][r] = v.z;
            As[c + 3][r] = v.w;
        }
#pragma unroll
        for (int i = 0; i < 4; i++) {
            int idx = (tid + i * 256) * 4;
            int r = idx >> 7;
            int c = idx & 127;
            *(float4*)&Bs[r][c] = *(const float4*)(W + (size_t)(kt + r) * 128 + c);
        }
        __syncthreads();

#pragma unroll
        for (int k = 0; k < 32; k++) {
            float4 a0 = *(float4*)&As[k][ty * 8];
            float4 a1 = *(float4*)&As[k][ty * 8 + 4];
            float4 b0 = *(float4*)&Bs[k][tx * 8];
            float4 b1 = *(float4*)&Bs[k][tx * 8 + 4];
            float a[8] = {a0.x, a0.y, a0.z, a0.w, a1.x, a1.y, a1.z, a1.w};
            float b[8] = {b0.x, b0.y, b0.z, b0.w, b1.x, b1.y, b1.z, b1.w};
#pragma unroll
            for (int i = 0; i < 8; i++)
#pragma unroll
                for (int j = 0; j < 8; j++)
                    acc[i][j] += a[i] * b[j];
        }
        __syncthreads();
    }

#pragma unroll
    for (int i = 0; i < 8; i++) {
        int gr = row0 + ty * 8 + i;
        if (gr >= M) continue;
#pragma unroll
        for (int jj = 0; jj < 2; jj++) {
            int c = tx * 8 + jj * 4;
            float4 o;
            o.x = fmaxf(acc[i][jj * 4 + 0] + bias[c + 0], 0.f);
            o.y = fmaxf(acc[i][jj * 4 + 1] + bias[c + 1], 0.f);
            o.z = fmaxf(acc[i][jj * 4 + 2] + bias[c + 2], 0.f);
            o.w = fmaxf(acc[i][jj * 4 + 3] + bias[c + 3], 0.f);
            *(float4*)(C + (size_t)gr * 128 + c) = o;
        }
    }
}

// ---------------------------------------------------------------------------
extern "C" void kernel_launch(void* const* d_in, const int* in_sizes, int n_in,
                              void* d_out, int out_size) {
    const float* x  = (const float*)d_in[0];
    const void*  ei = d_in[1];
    const float* W1 = (const float*)d_in[2];
    const float* b1 = (const float*)d_in[3];
    const float* W2 = (const float*)d_in[4];
    const float* b2 = (const float*)d_in[5];

    int N = in_sizes[0] / DDIM;
    int E = in_sizes[1] / 2;
    int L = in_sizes[3] / DDIM;   // b1 is [L, D]

    float* out = (float*)d_out;

    float *agg, *h, *xb;
    int *cnt, *rowptr, *cursor, *esrc;
    cudaGetSymbolAddress((void**)&agg,    g_agg);
    cudaGetSymbolAddress((void**)&h,      g_h);
    cudaGetSymbolAddress((void**)&xb,     g_x);
    cudaGetSymbolAddress((void**)&cnt,    g_cnt);
    cudaGetSymbolAddress((void**)&rowptr, g_rowptr);
    cudaGetSymbolAddress((void**)&cursor, g_cursor);
    cudaGetSymbolAddress((void**)&esrc,   g_esrc);

    // ---- CSR build (once per launch; edges identical across layers) ----
    zero_cnt_kernel<<<(N + 255) / 256, 256>>>(cnt, N);
    hist_kernel<<<(E + 255) / 256, 256>>>(cnt, ei, E, N);
    scan_kernel<<<1, 1024>>>(cnt, rowptr, cursor, N);
    bucket_kernel<<<(E + 255) / 256, 256>>>(cursor, esrc, ei, E, N);

    const float* cur = x;
    int gather_blocks = (N + 7) / 8;        // 8 warps / block, warp per node
    int gemm_blocks = (N + 127) / 128;

    for (int l = 0; l < L; l++) {
        gather_agg_kernel<<<gather_blocks, 256>>>(agg, cur, rowptr, esrc, N);
        gemm_bias_relu<<<gemm_blocks, 256>>>(agg, W1 + (size_t)l * DDIM * DDIM,
                                             b1 + (size_t)l * DDIM, h, N);
        float* dst = (l == L - 1) ? out : xb;
        gemm_bias_relu<<<gemm_blocks, 256>>>(h, W2 + (size_t)l * DDIM * DDIM,
                                             b2 + (size_t)l * DDIM, dst, N);
        cur = dst;
    }
}

// round 3
// speedup vs baseline: 2.6497x; 1.2926x over previous
#include <cuda_runtime.h>
#include <cstdint>

#define DDIM 128
#define MAXN 50048
#define MAXE 2097152
#define PADA 132   // padded row stride (floats) -> conflict-free fragment LDS

// Scratch (allocation-free: __device__ globals)
__device__ float g_agg[(size_t)MAXN * DDIM];
__device__ float g_h  [(size_t)MAXN * DDIM];
__device__ float g_x  [(size_t)MAXN * DDIM];
__device__ int   g_cnt[MAXN];
__device__ int   g_rowptr[MAXN + 1];
__device__ int   g_cursor[MAXN];
__device__ int   g_esrc[MAXE];

// ---------------------------------------------------------------------------
// Edge dtype self-detection (int64 vs int32)
// ---------------------------------------------------------------------------
__device__ __forceinline__ bool edges_are_i64(const void* ei, int N) {
    const long long* e64 = (const long long*)ei;
#pragma unroll
    for (int i = 0; i < 4; i++) {
        long long v = e64[i];
        if (v < 0 || v >= (long long)N) return false;
    }
    return true;
}

__global__ void zero_cnt_kernel(int* cnt, int n) {
    int i = blockIdx.x * blockDim.x + threadIdx.x;
    if (i < n) cnt[i] = 0;
}

__global__ void hist_kernel(int* cnt, const void* ei, int E, int N) {
    int i = blockIdx.x * blockDim.x + threadIdx.x;
    if (i >= E) return;
    bool is64 = edges_are_i64(ei, N);
    int d;
    if (is64) d = (int)((const long long*)ei)[E + i];
    else      d = ((const int*)ei)[E + i];
    atomicAdd(&cnt[d], 1);
}

__global__ void scan_kernel(const int* __restrict__ cnt, int* __restrict__ rowptr,
                            int* __restrict__ cursor, int N) {
    __shared__ int part[1024];
    int tid = threadIdx.x;
    int chunk = (N + 1023) / 1024;
    int start = tid * chunk;
    int end = min(start + chunk, N);
    int s = 0;
    for (int i = start; i < end; i++) s += cnt[i];
    part[tid] = s;
    __syncthreads();
    for (int off = 1; off < 1024; off <<= 1) {
        int v = (tid >= off) ? part[tid - off] : 0;
        __syncthreads();
        part[tid] += v;
        __syncthreads();
    }
    int run = (tid == 0) ? 0 : part[tid - 1];
    for (int i = start; i < end; i++) {
        rowptr[i] = run;
        cursor[i] = run;
        run += cnt[i];
    }
    if (end == N) rowptr[N] = run;
}

__global__ void bucket_kernel(int* __restrict__ cursor, int* __restrict__ esrc,
                              const void* ei, int E, int N) {
    int i = blockIdx.x * blockDim.x + threadIdx.x;
    if (i >= E) return;
    bool is64 = edges_are_i64(ei, N);
    int s, d;
    if (is64) {
        s = (int)((const long long*)ei)[i];
        d = (int)((const long long*)ei)[E + i];
    } else {
        s = ((const int*)ei)[i];
        d = ((const int*)ei)[E + i];
    }
    int pos = atomicAdd(&cursor[d], 1);
    esrc[pos] = s;
}

// ---------------------------------------------------------------------------
// agg[i] = x[i] + sum_{s in in-neighbors(i)} x[s].  One warp per node.
// ---------------------------------------------------------------------------
__global__ void gather_agg_kernel(float* __restrict__ agg, const float* __restrict__ x,
                                  const int* __restrict__ rowptr,
                                  const int* __restrict__ esrc, int N) {
    int node = blockIdx.x * (blockDim.x >> 5) + (threadIdx.x >> 5);
    if (node >= N) return;
    int lane = threadIdx.x & 31;

    float4 acc = ((const float4*)(x + (size_t)node * DDIM))[lane];
    int b = rowptr[node];
    int e = rowptr[node + 1];

    for (int base = b; base < e; base += 32) {
        int m = min(32, e - base);
        int sv = (lane < m) ? esrc[base + lane] : 0;
#pragma unroll 4
        for (int j = 0; j < m; j++) {
            int s = __shfl_sync(0xffffffffu, sv, j);
            float4 v = ((const float4*)(x + (size_t)s * DDIM))[lane];
            acc.x += v.x; acc.y += v.y; acc.z += v.z; acc.w += v.w;
        }
    }
    ((float4*)(agg + (size_t)node * DDIM))[lane] = acc;
}

// ---------------------------------------------------------------------------
// TF32 tensor-core GEMM:  C[M,128] = relu(A[M,128] @ W[128,128] + bias)
// Block tile 128x128, full K=128 staged in smem with tf32 rounding.
// 8 warps in 4(m) x 2(n); each warp 32x64 via 2x8 m16n8k8 tiles, 16 k-steps.
// ---------------------------------------------------------------------------
__device__ __forceinline__ uint32_t f2tf32(float f) {
    uint32_t r;
    asm("cvt.rna.tf32.f32 %0, %1;" : "=r"(r) : "f"(f));
    return r;
}

__global__ void __launch_bounds__(256)
gemm_tf32_bias_relu(const float* __restrict__ A, const float* __restrict__ W,
                    const float* __restrict__ bias, float* __restrict__ C, int M) {
    extern __shared__ uint32_t smem[];
    uint32_t* As = smem;                 // [128][PADA] tf32 bits
    uint32_t* Bs = smem + 128 * PADA;    // [128][PADA] tf32 bits (k-major)

    int tid = threadIdx.x;
    int row0 = blockIdx.x * 128;

    // Stage A (row-major) and W (k-major), converting to tf32.
    for (int i = tid; i < 4096; i += 256) {
        int r = i >> 5;                 // 32 float4 per row
        int c = (i & 31) << 2;
        float4 va = make_float4(0.f, 0.f, 0.f, 0.f);
        if (row0 + r < M) va = *(const float4*)(A + (size_t)(row0 + r) * DDIM + c);
        uint32_t* pa = &As[r * PADA + c];
        pa[0] = f2tf32(va.x); pa[1] = f2tf32(va.y);
        pa[2] = f2tf32(va.z); pa[3] = f2tf32(va.w);

        float4 vb = *(const float4*)(W + (size_t)r * DDIM + c);
        uint32_t* pb = &Bs[r * PADA + c];
        pb[0] = f2tf32(vb.x); pb[1] = f2tf32(vb.y);
        pb[2] = f2tf32(vb.z); pb[3] = f2tf32(vb.w);
    }
    __syncthreads();

    int wid = tid >> 5, lane = tid & 31;
    int g = lane >> 2, t = lane & 3;
    int wm = wid >> 1, wn = wid & 1;
    int mrow = wm * 32;      // warp row base within tile
    int ncol = wn * 64;      // warp col base

    float c_[2][8][4];
#pragma unroll
    for (int mt = 0; mt < 2; mt++)
#pragma unroll
        for (int nt = 0; nt < 8; nt++)
#pragma unroll
            for (int j = 0; j < 4; j++) c_[mt][nt][j] = 0.f;

#pragma unroll
    for (int ks = 0; ks < 16; ks++) {
        int k0 = ks * 8;
        uint32_t a[2][4], b[8][2];
#pragma unroll
        for (int mt = 0; mt < 2; mt++) {
            int r0 = (mrow + mt * 16 + g) * PADA + k0 + t;
            int r1 = (mrow + mt * 16 + g + 8) * PADA + k0 + t;
            a[mt][0] = As[r0];
            a[mt][1] = As[r1];
            a[mt][2] = As[r0 + 4];
            a[mt][3] = As[r1 + 4];
        }
#pragma unroll
        for (int nt = 0; nt < 8; nt++) {
            int cc = ncol + nt * 8 + g;
            b[nt][0] = Bs[(k0 + t) * PADA + cc];
            b[nt][1] = Bs[(k0 + t + 4) * PADA + cc];
        }
#pragma unroll
        for (int mt = 0; mt < 2; mt++)
#pragma unroll
            for (int nt = 0; nt < 8; nt++) {
                asm volatile(
                    "mma.sync.aligned.m16n8k8.row.col.f32.tf32.tf32.f32 "
                    "{%0,%1,%2,%3}, {%4,%5,%6,%7}, {%8,%9}, {%0,%1,%2,%3};\n"
                    : "+f"(c_[mt][nt][0]), "+f"(c_[mt][nt][1]),
                      "+f"(c_[mt][nt][2]), "+f"(c_[mt][nt][3])
                    : "r"(a[mt][0]), "r"(a[mt][1]), "r"(a[mt][2]), "r"(a[mt][3]),
                      "r"(b[nt][0]), "r"(b[nt][1]));
            }
    }

    // Epilogue: bias + relu
#pragma unroll
    for (int nt = 0; nt < 8; nt++) {
        int col = ncol + nt * 8 + t * 2;
        float2 bb = *(const float2*)(bias + col);
#pragma unroll
        for (int mt = 0; mt < 2; mt++) {
            int r0 = row0 + mrow + mt * 16 + g;
            int r1 = r0 + 8;
            if (r0 < M) {
                float2 o;
                o.x = fmaxf(c_[mt][nt][0] + bb.x, 0.f);
                o.y = fmaxf(c_[mt][nt][1] + bb.y, 0.f);
                *(float2*)(C + (size_t)r0 * DDIM + col) = o;
            }
            if (r1 < M) {
                float2 o;
                o.x = fmaxf(c_[mt][nt][2] + bb.x, 0.f);
                o.y = fmaxf(c_[mt][nt][3] + bb.y, 0.f);
                *(float2*)(C + (size_t)r1 * DDIM + col) = o;
            }
        }
    }
}

// ---------------------------------------------------------------------------
extern "C" void kernel_launch(void* const* d_in, const int* in_sizes, int n_in,
                              void* d_out, int out_size) {
    const float* x  = (const float*)d_in[0];
    const void*  ei = d_in[1];
    const float* W1 = (const float*)d_in[2];
    const float* b1 = (const float*)d_in[3];
    const float* W2 = (const float*)d_in[4];
    const float* b2 = (const float*)d_in[5];

    int N = in_sizes[0] / DDIM;
    int E = in_sizes[1] / 2;
    int L = in_sizes[3] / DDIM;

    float* out = (float*)d_out;

    float *agg, *h, *xb;
    int *cnt, *rowptr, *cursor, *esrc;
    cudaGetSymbolAddress((void**)&agg,    g_agg);
    cudaGetSymbolAddress((void**)&h,      g_h);
    cudaGetSymbolAddress((void**)&xb,     g_x);
    cudaGetSymbolAddress((void**)&cnt,    g_cnt);
    cudaGetSymbolAddress((void**)&rowptr, g_rowptr);
    cudaGetSymbolAddress((void**)&cursor, g_cursor);
    cudaGetSymbolAddress((void**)&esrc,   g_esrc);

    const int GEMM_SMEM = 2 * 128 * PADA * 4;   // 135168 B
    static int smem_set = 0;
    if (!smem_set) {
        cudaFuncSetAttribute(gemm_tf32_bias_relu,
                             cudaFuncAttributeMaxDynamicSharedMemorySize, GEMM_SMEM);
        smem_set = 1;
    }

    // ---- CSR build (once per launch) ----
    zero_cnt_kernel<<<(N + 255) / 256, 256>>>(cnt, N);
    hist_kernel<<<(E + 255) / 256, 256>>>(cnt, ei, E, N);
    scan_kernel<<<1, 1024>>>(cnt, rowptr, cursor, N);
    bucket_kernel<<<(E + 255) / 256, 256>>>(cursor, esrc, ei, E, N);

    const float* cur = x;
    int gather_blocks = (N + 7) / 8;
    int gemm_blocks = (N + 127) / 128;

    for (int l = 0; l < L; l++) {
        gather_agg_kernel<<<gather_blocks, 256>>>(agg, cur, rowptr, esrc, N);
        gemm_tf32_bias_relu<<<gemm_blocks, 256, GEMM_SMEM>>>(
            agg, W1 + (size_t)l * DDIM * DDIM, b1 + (size_t)l * DDIM, h, N);
        float* dst = (l == L - 1) ? out : xb;
        gemm_tf32_bias_relu<<<gemm_blocks, 256, GEMM_SMEM>>>(
            h, W2 + (size_t)l * DDIM * DDIM, b2 + (size_t)l * DDIM, dst, N);
        cur = dst;
    }
}

// round 6
// speedup vs baseline: 3.0377x; 1.1465x over previous
#include <cuda_runtime.h>
#include <cstdint>

#define DDIM 128
#define MAXN 50048
#define MAXE 2097152
#define PADB 132   // Bs row stride (tf32 words)
#define PADA 36    // As row stride (floats)

// Scratch (allocation-free: __device__ globals)
__device__ float g_agg[(size_t)MAXN * DDIM];
__device__ float g_h  [(size_t)MAXN * DDIM];
__device__ float g_x  [(size_t)MAXN * DDIM];
__device__ int   g_cnt[MAXN];
__device__ int   g_rowptr[MAXN + 1];
__device__ int   g_cursor[MAXN];
__device__ int   g_esrc[MAXE];

// ---------------------------------------------------------------------------
// Helpers
// ---------------------------------------------------------------------------
__device__ __forceinline__ uint32_t f2tf32(float f) {
    uint32_t r;
    asm("cvt.rna.tf32.f32 %0, %1;" : "=r"(r) : "f"(f));
    return r;
}
__device__ __forceinline__ uint32_t smem_u32(const void* p) {
    uint32_t a;
    asm("{ .reg .u64 t; cvta.to.shared.u64 t, %1; cvt.u32.u64 %0, t; }"
        : "=r"(a) : "l"(p));
    return a;
}
__device__ __forceinline__ void cp_async16(uint32_t dst, const void* src, bool pred) {
    int sz = pred ? 16 : 0;
    asm volatile("cp.async.ca.shared.global [%0], [%1], 16, %2;"
                 :: "r"(dst), "l"(src), "r"(sz));
}
__device__ __forceinline__ void cp_commit() {
    asm volatile("cp.async.commit_group;" ::: "memory");
}

__device__ __forceinline__ void mma_m16n8k8(float c[4], const uint32_t a[4],
                                            const uint32_t b[2]) {
    asm volatile(
        "mma.sync.aligned.m16n8k8.row.col.f32.tf32.tf32.f32 "
        "{%0,%1,%2,%3}, {%4,%5,%6,%7}, {%8,%9}, {%0,%1,%2,%3};\n"
        : "+f"(c[0]), "+f"(c[1]), "+f"(c[2]), "+f"(c[3])
        : "r"(a[0]), "r"(a[1]), "r"(a[2]), "r"(a[3]), "r"(b[0]), "r"(b[1]));
}

// ---------------------------------------------------------------------------
// Edge dtype self-detection (int64 vs int32)
// ---------------------------------------------------------------------------
__device__ __forceinline__ bool edges_are_i64(const void* ei, int N) {
    const long long* e64 = (const long long*)ei;
#pragma unroll
    for (int i = 0; i < 4; i++) {
        long long v = e64[i];
        if (v < 0 || v >= (long long)N) return false;
    }
    return true;
}

__global__ void zero_cnt_kernel(int* cnt, int n) {
    int i = blockIdx.x * blockDim.x + threadIdx.x;
    if (i < n) cnt[i] = 0;
}

__global__ void hist_kernel(int* cnt, const void* ei, int E, int N) {
    int i = blockIdx.x * blockDim.x + threadIdx.x;
    if (i >= E) return;
    bool is64 = edges_are_i64(ei, N);
    int d;
    if (is64) d = (int)((const long long*)ei)[E + i];
    else      d = ((const int*)ei)[E + i];
    atomicAdd(&cnt[d], 1);
}

__global__ void scan_kernel(const int* __restrict__ cnt, int* __restrict__ rowptr,
                            int* __restrict__ cursor, int N) {
    __shared__ int part[1024];
    int tid = threadIdx.x;
    int chunk = (N + 1023) / 1024;
    int start = tid * chunk;
    int end = min(start + chunk, N);
    int s = 0;
    for (int i = start; i < end; i++) s += cnt[i];
    part[tid] = s;
    __syncthreads();
    for (int off = 1; off < 1024; off <<= 1) {
        int v = (tid >= off) ? part[tid - off] : 0;
        __syncthreads();
        part[tid] += v;
        __syncthreads();
    }
    int run = (tid == 0) ? 0 : part[tid - 1];
    for (int i = start; i < end; i++) {
        rowptr[i] = run;
        cursor[i] = run;
        run += cnt[i];
    }
    if (end == N) rowptr[N] = run;
}

__global__ void bucket_kernel(int* __restrict__ cursor, int* __restrict__ esrc,
                              const void* ei, int E, int N) {
    int i = blockIdx.x * blockDim.x + threadIdx.x;
    if (i >= E) return;
    bool is64 = edges_are_i64(ei, N);
    int s, d;
    if (is64) {
        s = (int)((const long long*)ei)[i];
        d = (int)((const long long*)ei)[E + i];
    } else {
        s = ((const int*)ei)[i];
        d = ((const int*)ei)[E + i];
    }
    int pos = atomicAdd(&cursor[d], 1);
    esrc[pos] = s;
}

// ---------------------------------------------------------------------------
// agg[i] = x[i] + sum_{s in in-neighbors(i)} x[s].  One warp per node.
// ---------------------------------------------------------------------------
__global__ void gather_agg_kernel(float* __restrict__ agg, const float* __restrict__ x,
                                  const int* __restrict__ rowptr,
                                  const int* __restrict__ esrc, int N) {
    int node = blockIdx.x * (blockDim.x >> 5) + (threadIdx.x >> 5);
    if (node >= N) return;
    int lane = threadIdx.x & 31;

    float4 acc = ((const float4*)(x + (size_t)node * DDIM))[lane];
    int b = rowptr[node];
    int e = rowptr[node + 1];

    for (int base = b; base < e; base += 32) {
        int m = min(32, e - base);
        int sv = (lane < m) ? esrc[base + lane] : 0;
#pragma unroll 4
        for (int j = 0; j < m; j++) {
            int s = __shfl_sync(0xffffffffu, sv, j);
            float4 v = ((const float4*)(x + (size_t)s * DDIM))[lane];
            acc.x += v.x; acc.y += v.y; acc.z += v.z; acc.w += v.w;
        }
    }
    ((float4*)(agg + (size_t)node * DDIM))[lane] = acc;
}

// ---------------------------------------------------------------------------
// Persistent pipelined tf32 mma.sync GEMM:
//   C[M,128] = relu(A[M,128] @ W[128,128] + bias)
// W staged once per block (tf32, k-major). A staged fp32 via cp.async in 4
// chunks of 128x32 (all prefetched, drained with wait_group 3..0), cvt.rna
// applied per-fragment. 8 warps, 4(m)x2(n), 32x64 each via 2x8 m16n8k8.
// ---------------------------------------------------------------------------
#define SM_BIAS  0
#define SM_B     128                             // floats offset
#define SM_A     (128 + 128 * PADB)              // floats offset
#define GEMM_SMEM ((128 + 128 * PADB + 4 * 128 * PADA) * 4)

template <int WAIT>
__device__ __forceinline__ void compute_chunk(
    const float* __restrict__ As_c, const uint32_t* __restrict__ Bs, int kbase,
    int mrow, int ncol, int g, int t, float acc[2][8][4]) {
    asm volatile("cp.async.wait_group %0;" :: "n"(WAIT) : "memory");
    __syncthreads();
#pragma unroll
    for (int ks = 0; ks < 4; ks++) {
        int kk = ks * 8;
        uint32_t a[2][4];
#pragma unroll
        for (int mt = 0; mt < 2; mt++) {
            const float* b0 = As_c + (mrow + mt * 16 + g) * PADA + kk + t;
            const float* b1 = As_c + (mrow + mt * 16 + g + 8) * PADA + kk + t;
            a[mt][0] = f2tf32(b0[0]);
            a[mt][1] = f2tf32(b1[0]);
            a[mt][2] = f2tf32(b0[4]);
            a[mt][3] = f2tf32(b1[4]);
        }
        uint32_t b[8][2];
#pragma unroll
        for (int nt = 0; nt < 8; nt++) {
            int cc = ncol + nt * 8 + g;
            b[nt][0] = Bs[(kbase + kk + t) * PADB + cc];
            b[nt][1] = Bs[(kbase + kk + t + 4) * PADB + cc];
        }
#pragma unroll
        for (int mt = 0; mt < 2; mt++)
#pragma unroll
            for (int nt = 0; nt < 8; nt++)
                mma_m16n8k8(acc[mt][nt], a[mt], b[nt]);
    }
}

__global__ void __launch_bounds__(256, 1)
gemm_tf32_pipe(const float* __restrict__ A, const float* __restrict__ W,
               const float* __restrict__ bias, float* __restrict__ C,
               int M, int ntiles) {
    extern __shared__ float sm[];
    float* bias_s = sm + SM_BIAS;
    uint32_t* Bs = (uint32_t*)(sm + SM_B);
    float* As = sm + SM_A;                       // [4][128][PADA]

    int tid = threadIdx.x;
    int wid = tid >> 5, lane = tid & 31;
    int g = lane >> 2, t = lane & 3;
    int mrow = (wid >> 1) * 32, ncol = (wid & 1) * 64;

    if (tid < 128) bias_s[tid] = bias[tid];
    // Stage W once (k-major, tf32)
    for (int i = tid; i < 4096; i += 256) {
        int k = i >> 5;
        int n4 = (i & 31) << 2;
        float4 v = *(const float4*)(W + (size_t)k * DDIM + n4);
        uint32_t* p = &Bs[k * PADB + n4];
        p[0] = f2tf32(v.x); p[1] = f2tf32(v.y);
        p[2] = f2tf32(v.z); p[3] = f2tf32(v.w);
    }
    __syncthreads();

    for (int tt = blockIdx.x; tt < ntiles; tt += gridDim.x) {
        int row0 = tt << 7;
        __syncthreads();   // all warps done reading As from previous tile

        // Prologue: prefetch all 4 A chunks (128 rows x 32 k each)
#pragma unroll
        for (int c = 0; c < 4; c++) {
#pragma unroll
            for (int j = 0; j < 4; j++) {
                int i = tid + j * 256;           // 0..1023
                int r = i >> 3;
                int cc = (i & 7) << 2;
                uint32_t dst = smem_u32(&As[(c * 128 + r) * PADA + cc]);
                const float* src = A + (size_t)(row0 + r) * DDIM + c * 32 + cc;
                cp_async16(dst, src, row0 + r < M);
            }
            cp_commit();
        }

        float acc[2][8][4];
#pragma unroll
        for (int mt = 0; mt < 2; mt++)
#pragma unroll
            for (int nt = 0; nt < 8; nt++)
#pragma unroll
                for (int j = 0; j < 4; j++) acc[mt][nt][j] = 0.f;

        compute_chunk<3>(As + 0 * 128 * PADA, Bs, 0,  mrow, ncol, g, t, acc);
        compute_chunk<2>(As + 1 * 128 * PADA, Bs, 32, mrow, ncol, g, t, acc);
        compute_chunk<1>(As + 2 * 128 * PADA, Bs, 64, mrow, ncol, g, t, acc);
        compute_chunk<0>(As + 3 * 128 * PADA, Bs, 96, mrow, ncol, g, t, acc);

        // Epilogue: bias + relu
#pragma unroll
        for (int nt = 0; nt < 8; nt++) {
            int col = ncol + nt * 8 + t * 2;
            float2 bb = *(const float2*)(bias_s + col);
#pragma unroll
            for (int mt = 0; mt < 2; mt++) {
                int r0 = row0 + mrow + mt * 16 + g;
                int r1 = r0 + 8;
                if (r0 < M) {
                    float2 o;
                    o.x = fmaxf(acc[mt][nt][0] + bb.x, 0.f);
                    o.y = fmaxf(acc[mt][nt][1] + bb.y, 0.f);
                    *(float2*)(C + (size_t)r0 * DDIM + col) = o;
                }
                if (r1 < M) {
                    float2 o;
                    o.x = fmaxf(acc[mt][nt][2] + bb.x, 0.f);
                    o.y = fmaxf(acc[mt][nt][3] + bb.y, 0.f);
                    *(float2*)(C + (size_t)r1 * DDIM + col) = o;
                }
            }
        }
    }
}

// ---------------------------------------------------------------------------
extern "C" void kernel_launch(void* const* d_in, const int* in_sizes, int n_in,
                              void* d_out, int out_size) {
    const float* x  = (const float*)d_in[0];
    const void*  ei = d_in[1];
    const float* W1 = (const float*)d_in[2];
    const float* b1 = (const float*)d_in[3];
    const float* W2 = (const float*)d_in[4];
    const float* b2 = (const float*)d_in[5];

    int N = in_sizes[0] / DDIM;
    int E = in_sizes[1] / 2;
    int L = in_sizes[3] / DDIM;

    float* out = (float*)d_out;

    float *agg, *h, *xb;
    int *cnt, *rowptr, *cursor, *esrc;
    cudaGetSymbolAddress((void**)&agg,    g_agg);
    cudaGetSymbolAddress((void**)&h,      g_h);
    cudaGetSymbolAddress((void**)&xb,     g_x);
    cudaGetSymbolAddress((void**)&cnt,    g_cnt);
    cudaGetSymbolAddress((void**)&rowptr, g_rowptr);
    cudaGetSymbolAddress((void**)&cursor, g_cursor);
    cudaGetSymbolAddress((void**)&esrc,   g_esrc);

    static int smem_set = 0;
    if (!smem_set) {
        cudaFuncSetAttribute(gemm_tf32_pipe,
                             cudaFuncAttributeMaxDynamicSharedMemorySize, GEMM_SMEM);
        smem_set = 1;
    }

    // ---- CSR build (once per launch) ----
    zero_cnt_kernel<<<(N + 255) / 256, 256>>>(cnt, N);
    hist_kernel<<<(E + 255) / 256, 256>>>(cnt, ei, E, N);
    scan_kernel<<<1, 1024>>>(cnt, rowptr, cursor, N);
    bucket_kernel<<<(E + 255) / 256, 256>>>(cursor, esrc, ei, E, N);

    const float* cur = x;
    int gather_blocks = (N + 7) / 8;
    int ntiles = (N + 127) / 128;
    int gemm_grid = ntiles < 148 ? ntiles : 148;

    for (int l = 0; l < L; l++) {
        gather_agg_kernel<<<gather_blocks, 256>>>(agg, cur, rowptr, esrc, N);
        gemm_tf32_pipe<<<gemm_grid, 256, GEMM_SMEM>>>(
            agg, W1 + (size_t)l * DDIM * DDIM, b1 + (size_t)l * DDIM, h, N, ntiles);
        float* dst = (l == L - 1) ? out : xb;
        gemm_tf32_pipe<<<gemm_grid, 256, GEMM_SMEM>>>(
            h, W2 + (size_t)l * DDIM * DDIM, b2 + (size_t)l * DDIM, dst, N, ntiles);
        cur = dst;
    }
}